// round 3
// baseline (speedup 1.0000x reference)
#include <cuda_runtime.h>
#include <cstdint>
#include <cstddef>

// Problem constants
#define TT   1024
#define BB   512
#define II   32
#define HH   256
#define OO   32
#define KDIM 288      // H + I

#define NGRP 16       // batch groups (32 rows each)
#define GCTA 8        // CTAs per group (each owns 32 j-indices)
#define BT   32       // batch rows per group (= lanes)
#define JT   32       // j-indices per CTA
#define NTHR 256      // 8 warps per CTA

#define WST   132     // w_t row stride (k-major): (4k+r)%32 conflict-free, 528B = 33*16 aligned
#define HXST  36      // hx row stride: (4k+b)%32 conflict-free, 144B 16-aligned
#define WOUTST 260

// Persistent scratch (no allocation allowed)
__device__ __align__(16) float    g_h[2][NGRP][HH][BT];   // transposed hidden state [par][grp][j][b]
__device__ unsigned               g_bar[NGRP];            // per-group monotonic barrier counters

__global__ void init_kernel() {
    int idx = blockIdx.x * blockDim.x + threadIdx.x;
    if (idx < NGRP * HH * BT) ((float*)g_h)[idx] = 0.0f;  // zero h^(0) (parity 0)
    if (idx < NGRP) g_bar[idx] = 0u;
}

typedef unsigned long long ull;

__device__ __forceinline__ void ffma2(ull& acc, ull a, ull b) {
    asm volatile("fma.rn.f32x2 %0, %1, %2, %0;" : "+l"(acc) : "l"(a), "l"(b));
}
__device__ __forceinline__ ull pack2(float a, float b) {
    ull r; asm("mov.b64 %0, {%1, %2};" : "=l"(r) : "f"(a), "f"(b)); return r;
}
__device__ __forceinline__ float2 unpack2(ull v) {
    float2 r; asm("mov.b64 {%0, %1}, %2;" : "=f"(r.x), "=f"(r.y) : "l"(v)); return r;
}
__device__ __forceinline__ unsigned ld_acquire_u32(const unsigned* p) {
    unsigned v;
    asm volatile("ld.acquire.gpu.u32 %0, [%1];" : "=r"(v) : "l"(p));
    return v;
}
__device__ __forceinline__ float sigf(float x) {
    return __fdividef(1.0f, 1.0f + __expf(-x));
}
__device__ __forceinline__ float tanh_fast(float x) {
    float ax = fabsf(x);
    float e  = __expf(-2.0f * ax);                 // e in (0,1], no overflow
    float r  = __fdividef(1.0f - e, 1.0f + e);
    return copysignf(r, x);
}

__global__ void __launch_bounds__(NTHR, 1)
lstm_kernel(const float* __restrict__ x, const float* __restrict__ phys,
            const float* __restrict__ Wih, const float* __restrict__ Whh,
            const float* __restrict__ bih, const float* __restrict__ bhh,
            const float* __restrict__ Wout, const float* __restrict__ bout,
            float* __restrict__ out) {
    extern __shared__ float smem[];
    float* w_s    = smem;                    // [KDIM][WST]   transposed weights, r = jj*4 + q
    float* hx     = w_s + KDIM * WST;        // [KDIM][HXST]  h(t) ++ x(t), transposed [k][b]
    float* wout_s = hx + KDIM * HXST;        // [4][WOUTST]
    float* bout_s = wout_s + 4 * WOUTST;     // [4]

    const int tid  = threadIdx.x;
    const int cta  = blockIdx.x;
    const int grp  = cta >> 3;               // batch group 0..15
    const int g8   = cta & 7;                // j-slice within group 0..7
    const int b0   = grp * BT;
    const int j0   = g8 * JT;
    const int w    = tid >> 5;               // warp 0..7 -> owns jj in [w*4, w*4+4)
    const int lane = tid & 31;               // lane = batch within group

    // ---- one-time: weights transposed into smem ----
    for (int i = tid; i < 128 * KDIM; i += NTHR) {
        int r = i / KDIM, k = i - r * KDIM;
        int q = r & 3, jj = r >> 2;
        int grow = q * HH + j0 + jj;
        float v = (k < HH) ? Whh[grow * HH + k] : Wih[grow * II + (k - HH)];
        w_s[k * WST + r] = v;
    }
    for (int i = tid; i < 4 * HH; i += NTHR) {
        int o = i >> 8, k = i & 255;
        wout_s[o * WOUTST + k] = Wout[(g8 * 4 + o) * HH + k];
    }
    if (tid < 4) bout_s[tid] = bout[g8 * 4 + tid];

    // biases pre-packed into accumulator-init registers
    ull bias01[4], bias23[4];
#pragma unroll
    for (int jt = 0; jt < 4; ++jt) {
        int gj = j0 + w * 4 + jt;
        bias01[jt] = pack2(bih[0 * HH + gj] + bhh[0 * HH + gj],
                           bih[1 * HH + gj] + bhh[1 * HH + gj]);
        bias23[jt] = pack2(bih[2 * HH + gj] + bhh[2 * HH + gj],
                           bih[3 * HH + gj] + bhh[3 * HH + gj]);
    }

    float c[4] = {0.f, 0.f, 0.f, 0.f};       // cell state in registers
    __syncthreads();

    for (int t = 0; t <= TT; ++t) {
        // ---- stage h(t) (transposed, coalesced both ends) ----
        const float* hsrc = &g_h[t & 1][grp][0][0];
#pragma unroll
        for (int i = tid; i < HH * BT / 4; i += NTHR) {      // 2048 float4
            float4 v = ((const float4*)hsrc)[i];
            int k = i >> 3, b4 = (i & 7) * 4;
            *(float4*)(hx + k * HXST + b4) = v;
        }
        // ---- stage x(t) ----
        if (t < TT) {
            int b = tid >> 3, k4 = (tid & 7) * 4;            // one float4 per thread
            float4 v = *(const float4*)(x + ((size_t)t * BB + b0 + b) * II + k4);
            hx[(HH + k4 + 0) * HXST + b] = v.x;
            hx[(HH + k4 + 1) * HXST + b] = v.y;
            hx[(HH + k4 + 2) * HXST + b] = v.z;
            hx[(HH + k4 + 3) * HXST + b] = v.w;
        }
        __syncthreads();

        // ---- output projection for step t-1 (h(t) just staged == h after step t-1) ----
        if (t > 0 && tid < 128) {
            int b = tid >> 2, o = tid & 3;
            const float* hp = hx + b;
            const float* wp = wout_s + o * WOUTST;
            float a0 = 0.f, a1 = 0.f, a2 = 0.f, a3 = 0.f;
#pragma unroll 16
            for (int jv = 0; jv < HH; jv += 4) {
                a0 = fmaf(hp[(jv + 0) * HXST], wp[jv + 0], a0);
                a1 = fmaf(hp[(jv + 1) * HXST], wp[jv + 1], a1);
                a2 = fmaf(hp[(jv + 2) * HXST], wp[jv + 2], a2);
                a3 = fmaf(hp[(jv + 3) * HXST], wp[jv + 3], a3);
            }
            float rnn = (a0 + a1) + (a2 + a3) + bout_s[o];
            int tm1 = t - 1, bg = b0 + b, oc = g8 * 4 + o;
            float ph = phys[((size_t)tm1 * BB + bg) * OO + oc];
            size_t oi = ((size_t)bg * TT + tm1) * OO + oc;
            out[oi] = ph + rnn;                               // full_pred [B,T,O]
            out[(size_t)BB * TT * OO + oi] = rnn;             // rnn_pred  [B,T,O]
        }
        if (t == TT) break;

        // ---- gate GEMM: lanes = batch, weights broadcast, bias pre-folded ----
        ull acc[4][2];
#pragma unroll
        for (int jt = 0; jt < 4; ++jt) { acc[jt][0] = bias01[jt]; acc[jt][1] = bias23[jt]; }

        const float* hcol  = hx + lane;
        const float* wbase = w_s + w * 16;
#pragma unroll 4
        for (int k = 0; k < KDIM; ++k) {
            float hk = hcol[k * HXST];
            ull h2 = pack2(hk, hk);
            const float* wk = wbase + k * WST;
            ulonglong2 w0 = *(const ulonglong2*)(wk);
            ulonglong2 w1 = *(const ulonglong2*)(wk + 4);
            ulonglong2 w2 = *(const ulonglong2*)(wk + 8);
            ulonglong2 w3 = *(const ulonglong2*)(wk + 12);
            ffma2(acc[0][0], h2, w0.x); ffma2(acc[0][1], h2, w0.y);
            ffma2(acc[1][0], h2, w1.x); ffma2(acc[1][1], h2, w1.y);
            ffma2(acc[2][0], h2, w2.x); ffma2(acc[2][1], h2, w2.y);
            ffma2(acc[3][0], h2, w3.x); ffma2(acc[3][1], h2, w3.y);
        }

        // ---- LSTM elementwise update, c in regs, h store coalesced ----
        float* hdst = &g_h[(t + 1) & 1][grp][0][0];
#pragma unroll
        for (int jt = 0; jt < 4; ++jt) {
            float2 a01 = unpack2(acc[jt][0]);   // (gi, gf)
            float2 a23 = unpack2(acc[jt][1]);   // (gg, go)
            float ig = sigf(a01.x);
            float fg = sigf(a01.y);
            float gt = tanh_fast(a23.x);
            float og = sigf(a23.y);
            float cn = fg * c[jt] + ig * gt;
            float hn = og * tanh_fast(cn);
            c[jt] = cn;
            hdst[(j0 + w * 4 + jt) * BT + lane] = hn;
        }

        // ---- group barrier (8 CTAs), monotonic counter ----
        __threadfence();
        __syncthreads();
        if (tid == 0) {
            atomicAdd(&g_bar[grp], 1u);
            unsigned target = 8u * (unsigned)(t + 1);
            while (ld_acquire_u32(&g_bar[grp]) < target) { }
        }
        __syncthreads();
    }
}

extern "C" void kernel_launch(void* const* d_in, const int* in_sizes, int n_in,
                              void* d_out, int out_size) {
    const float* x    = (const float*)d_in[0];
    const float* phys = (const float*)d_in[1];
    const float* Wih  = (const float*)d_in[2];
    const float* Whh  = (const float*)d_in[3];
    const float* bih  = (const float*)d_in[4];
    const float* bhh  = (const float*)d_in[5];
    const float* Wout = (const float*)d_in[6];
    const float* bout = (const float*)d_in[7];
    float* out = (float*)d_out;

    size_t smem_bytes = (size_t)(KDIM * WST + KDIM * HXST + 4 * WOUTST + 4) * sizeof(float);

    cudaFuncSetAttribute(lstm_kernel,
                         cudaFuncAttributeMaxDynamicSharedMemorySize,
                         (int)smem_bytes);

    init_kernel<<<(NGRP * HH * BT + 255) / 256, 256>>>();
    lstm_kernel<<<NGRP * GCTA, NTHR, smem_bytes>>>(x, phys, Wih, Whh, bih, bhh,
                                                   Wout, bout, out);
}

// round 5
// speedup vs baseline: 1.3797x; 1.3797x over previous
#include <cuda_runtime.h>
#include <cstdint>
#include <cstddef>

// Problem constants
#define TT   1024
#define BB   512
#define II   32
#define HH   256
#define OO   32
#define KDIM 288      // H + I
#define KHALF 144

#define NGRP 16       // batch groups (32 rows each)
#define BT   32       // batch rows per group
#define JT   32       // j-indices per CTA (lanes)
#define NTHR 256      // 8 warps: 4 batch-octets x 2 k-halves

typedef unsigned long long ull;

// Persistent scratch (no allocation allowed)
__device__ __align__(16) float    g_h[2][NGRP][HH][BT];   // hidden state [par][grp][j][b]
__device__ unsigned               g_bar[NGRP];            // per-group monotonic barrier counters

__global__ void init_kernel() {
    int idx = blockIdx.x * blockDim.x + threadIdx.x;
    if (idx < NGRP * HH * BT) ((float*)g_h)[idx] = 0.0f;  // zero h^(0) (parity 0)
    if (idx < NGRP) g_bar[idx] = 0u;
}

__device__ __forceinline__ void ffma2(ull& acc, ull a, ull b) {
    asm("fma.rn.f32x2 %0, %1, %2, %0;" : "+l"(acc) : "l"(a), "l"(b));
}
__device__ __forceinline__ void add2(ull& a, ull b) {
    asm("add.rn.f32x2 %0, %0, %1;" : "+l"(a) : "l"(b));
}
__device__ __forceinline__ ull pack2(float a, float b) {
    ull r; asm("mov.b64 %0, {%1, %2};" : "=l"(r) : "f"(a), "f"(b)); return r;
}
__device__ __forceinline__ float2 unpack2(ull v) {
    float2 r; asm("mov.b64 {%0, %1}, %2;" : "=f"(r.x), "=f"(r.y) : "l"(v)); return r;
}
__device__ __forceinline__ unsigned ld_acquire_u32(const unsigned* p) {
    unsigned v;
    asm volatile("ld.acquire.gpu.u32 %0, [%1];" : "=r"(v) : "l"(p));
    return v;
}
__device__ __forceinline__ float sigf(float x) {
    return __fdividef(1.0f, 1.0f + __expf(-x));
}
__device__ __forceinline__ float tanh_acc(float x) {
    float ax = fabsf(x);
    float e  = __expf(-2.0f * ax);                 // e in (0,1], no overflow
    float r  = __fdividef(1.0f - e, 1.0f + e);
    return copysignf(r, x);
}

// smem layout (floats)
#define OFF_W     0                        // [KDIM][32 j][4 gates] = 36864
#define OFF_HX    36864                    // [KDIM][32 b]          = 9216
#define OFF_WOUT  (OFF_HX + 9216)          // [256 j][4 o]          = 1024
#define OFF_RED1  (OFF_WOUT + 1024)        // gemm partials: 128 thr x 16 ull = 4096 floats
#define OFF_RED2  (OFF_RED1 + 4096)        // outproj partials: 256 thr x 8 ull = 4096 floats
#define OFF_BOUT  (OFF_RED2 + 4096)        // 4 (+4 pad)
#define SMEM_FLOATS (OFF_BOUT + 8)         // 55304 floats = 221,216 B (< 227 KB cap)

__global__ void __launch_bounds__(NTHR, 1)
lstm_kernel(const float* __restrict__ x, const float* __restrict__ phys,
            const float* __restrict__ Wih, const float* __restrict__ Whh,
            const float* __restrict__ bih, const float* __restrict__ bhh,
            const float* __restrict__ Wout, const float* __restrict__ bout,
            float* __restrict__ out) {
    extern __shared__ float smem[];
    float* w_s    = smem + OFF_W;
    float* hx     = smem + OFF_HX;
    float* wout2  = smem + OFF_WOUT;
    ull*   red1   = (ull*)(smem + OFF_RED1);
    ull*   red2   = (ull*)(smem + OFF_RED2);
    float* bout_s = smem + OFF_BOUT;

    const int tid  = threadIdx.x;
    const int cta  = blockIdx.x;
    const int grp  = cta >> 3;               // batch group 0..15
    const int g8   = cta & 7;                // j-slice 0..7
    const int b0   = grp * BT;
    const int j0   = g8 * JT;
    const int lane = tid & 31;               // lane = j within slice
    const int oct  = (tid >> 5) & 3;         // batch octet 0..3
    const int kh   = tid >> 7;               // k-half 0/1

    // ---- one-time: weights [k][j][g] ----
    for (int i = tid; i < KDIM * 128; i += NTHR) {
        int k = i >> 7, r = i & 127;
        int j = r >> 2, g = r & 3;
        int grow = g * HH + j0 + j;
        float v = (k < HH) ? Whh[grow * HH + k] : Wih[grow * II + (k - HH)];
        w_s[(k << 7) + (j << 2) + g] = v;
    }
    for (int i = tid; i < HH * 4; i += NTHR) {
        int k = i >> 2, o = i & 3;
        wout2[(k << 2) + o] = Wout[(g8 * 4 + o) * HH + k];
    }
    if (tid < 4) bout_s[tid] = bout[g8 * 4 + tid];

    // bias (kh=0 threads fold it into their accumulator init), packed dup per gate
    ull biasd[4];
#pragma unroll
    for (int g = 0; g < 4; ++g) {
        int gj = g * HH + j0 + lane;
        float bv = bih[gj] + bhh[gj];
        biasd[g] = pack2(bv, bv);
    }

    float c[8] = {0.f,0.f,0.f,0.f,0.f,0.f,0.f,0.f};   // cell state (kh=0 threads)
    __syncthreads();

    for (int t = 0; t <= TT; ++t) {
        // ---- stage h(t) into hx[k][b] + out-projection partials (register reuse) ----
        ull p2[4][2];
#pragma unroll
        for (int o = 0; o < 4; ++o) { p2[o][0] = 0ull; p2[o][1] = 0ull; }
        {
            const float4* hsrc4 = (const float4*)&g_h[t & 1][grp][0][0];
#pragma unroll
            for (int it = 0; it < 8; ++it) {
                int idx = it * NTHR + tid;
                float4 v = hsrc4[idx];
                int k = idx >> 3, b4 = idx & 7;
                *(float4*)(hx + (k << 5) + (b4 << 2)) = v;
                float4 wo = *(const float4*)(wout2 + (k << 2));
                ull vlo = pack2(v.x, v.y), vhi = pack2(v.z, v.w);
                ull w0 = pack2(wo.x, wo.x), w1 = pack2(wo.y, wo.y);
                ull w2 = pack2(wo.z, wo.z), w3 = pack2(wo.w, wo.w);
                ffma2(p2[0][0], vlo, w0); ffma2(p2[0][1], vhi, w0);
                ffma2(p2[1][0], vlo, w1); ffma2(p2[1][1], vhi, w1);
                ffma2(p2[2][0], vlo, w2); ffma2(p2[2][1], vhi, w2);
                ffma2(p2[3][0], vlo, w3); ffma2(p2[3][1], vhi, w3);
            }
        }
        if (t < TT) {   // stage x(t): thread -> one float4
            int b = tid >> 3, kk4 = (tid & 7) << 2;
            float4 v = *(const float4*)(x + ((size_t)t * BB + b0 + b) * II + kk4);
            hx[(HH + kk4 + 0) * 32 + b] = v.x;
            hx[(HH + kk4 + 1) * 32 + b] = v.y;
            hx[(HH + kk4 + 2) * 32 + b] = v.z;
            hx[(HH + kk4 + 3) * 32 + b] = v.w;
        }
        {   // stash out-proj partials (256 thr x 8 ull = full red2 region)
            ull* q = red2 + tid * 8;
#pragma unroll
            for (int o = 0; o < 4; ++o) { q[o * 2] = p2[o][0]; q[o * 2 + 1] = p2[o][1]; }
        }
        __syncthreads();

        ull acc[4][4];
        if (t < TT) {
            // ---- gate GEMM over this warp's k-half ----
#pragma unroll
            for (int g = 0; g < 4; ++g)
#pragma unroll
                for (int bp = 0; bp < 4; ++bp)
                    acc[g][bp] = kh ? 0ull : biasd[g];

            const float* hb = hx + oct * 8;
            const int kbeg = kh * KHALF, kend = kbeg + KHALF;
#pragma unroll 4
            for (int k = kbeg; k < kend; ++k) {
                float4 w4 = *(const float4*)(w_s + (k << 7) + (lane << 2));
                ulonglong2 h01 = *(const ulonglong2*)(hb + (k << 5));
                ulonglong2 h23 = *(const ulonglong2*)(hb + (k << 5) + 4);
                ull w0 = pack2(w4.x, w4.x), w1 = pack2(w4.y, w4.y);
                ull w2 = pack2(w4.z, w4.z), w3 = pack2(w4.w, w4.w);
                ffma2(acc[0][0], h01.x, w0); ffma2(acc[0][1], h01.y, w0);
                ffma2(acc[0][2], h23.x, w0); ffma2(acc[0][3], h23.y, w0);
                ffma2(acc[1][0], h01.x, w1); ffma2(acc[1][1], h01.y, w1);
                ffma2(acc[1][2], h23.x, w1); ffma2(acc[1][3], h23.y, w1);
                ffma2(acc[2][0], h01.x, w2); ffma2(acc[2][1], h01.y, w2);
                ffma2(acc[2][2], h23.x, w2); ffma2(acc[2][3], h23.y, w2);
                ffma2(acc[3][0], h01.x, w3); ffma2(acc[3][1], h01.y, w3);
                ffma2(acc[3][2], h23.x, w3); ffma2(acc[3][3], h23.y, w3);
            }
            if (kh) {   // stash k-half-1 partials (128 thr x 16 ull = full red1 region)
                ull* q = red1 + (tid - 128) * 16;
#pragma unroll
                for (int g = 0; g < 4; ++g)
#pragma unroll
                    for (int bp = 0; bp < 4; ++bp) q[g * 4 + bp] = acc[g][bp];
            }
        }
        __syncthreads();

        // ---- out-projection finalize for step t-1 (kh=1 warps, concurrent w/ epilogue) ----
        if (kh && t > 0) {
            int u = tid & 127;
            int o = u >> 5, b = u & 31;
            int b4 = b >> 2, bp = (b >> 1) & 1, e = b & 1;
            ull s = 0ull;
#pragma unroll 8
            for (int m = 0; m < 32; ++m)
                add2(s, red2[(b4 + (m << 3)) * 8 + o * 2 + bp]);
            float2 sf = unpack2(s);
            float rnn = (e ? sf.y : sf.x) + bout_s[o];
            int tm1 = t - 1, bg = b0 + b, ocl = g8 * 4 + o;
            float ph = phys[((size_t)tm1 * BB + bg) * OO + ocl];
            size_t oi = ((size_t)bg * TT + tm1) * OO + ocl;
            out[oi] = ph + rnn;                               // full_pred [B,T,O]
            out[(size_t)BB * TT * OO + oi] = rnn;             // rnn_pred  [B,T,O]
        }
        if (t == TT) break;

        // ---- kh=0: cross-k-half reduce, LSTM epilogue, h writeback ----
        if (!kh) {
            const ull* q = red1 + tid * 16;
#pragma unroll
            for (int g = 0; g < 4; ++g)
#pragma unroll
                for (int bp = 0; bp < 4; ++bp) add2(acc[g][bp], q[g * 4 + bp]);

            float hv[8];
#pragma unroll
            for (int bp = 0; bp < 4; ++bp) {
                float2 gi = unpack2(acc[0][bp]);
                float2 gf = unpack2(acc[1][bp]);
                float2 gg = unpack2(acc[2][bp]);
                float2 go = unpack2(acc[3][bp]);
                {
                    float ig = sigf(gi.x), fg = sigf(gf.x);
                    float gt = tanh_acc(gg.x), og = sigf(go.x);
                    float cn = fg * c[bp * 2] + ig * gt;
                    c[bp * 2] = cn; hv[bp * 2] = og * tanh_acc(cn);
                }
                {
                    float ig = sigf(gi.y), fg = sigf(gf.y);
                    float gt = tanh_acc(gg.y), og = sigf(go.y);
                    float cn = fg * c[bp * 2 + 1] + ig * gt;
                    c[bp * 2 + 1] = cn; hv[bp * 2 + 1] = og * tanh_acc(cn);
                }
            }
            float* hd = &g_h[(t + 1) & 1][grp][0][0] + ((j0 + lane) << 5) + oct * 8;
            *(float4*)hd       = make_float4(hv[0], hv[1], hv[2], hv[3]);
            *(float4*)(hd + 4) = make_float4(hv[4], hv[5], hv[6], hv[7]);
        }

        // ---- group barrier (8 CTAs), monotonic counter ----
        __threadfence();
        __syncthreads();
        if (tid == 0) {
            atomicAdd(&g_bar[grp], 1u);
            unsigned target = 8u * (unsigned)(t + 1);
            while (ld_acquire_u32(&g_bar[grp]) < target) { }
        }
        __syncthreads();
    }
}

extern "C" void kernel_launch(void* const* d_in, const int* in_sizes, int n_in,
                              void* d_out, int out_size) {
    const float* x    = (const float*)d_in[0];
    const float* phys = (const float*)d_in[1];
    const float* Wih  = (const float*)d_in[2];
    const float* Whh  = (const float*)d_in[3];
    const float* bih  = (const float*)d_in[4];
    const float* bhh  = (const float*)d_in[5];
    const float* Wout = (const float*)d_in[6];
    const float* bout = (const float*)d_in[7];
    float* out = (float*)d_out;

    size_t smem_bytes = (size_t)SMEM_FLOATS * sizeof(float);   // 221,216 B

    cudaFuncSetAttribute(lstm_kernel,
                         cudaFuncAttributeMaxDynamicSharedMemorySize,
                         (int)smem_bytes);

    init_kernel<<<(NGRP * HH * BT + 255) / 256, 256>>>();
    lstm_kernel<<<NGRP * 8, NTHR, smem_bytes>>>(x, phys, Wih, Whh, bih, bhh,
                                                Wout, bout, out);
}